// round 1
// baseline (speedup 1.0000x reference)
#include <cuda_runtime.h>
#include <math.h>

#define NS   8
#define KK   3
#define C    512
#define CB   128
#define NB   8
#define HW   1024          // 32*32
#define HW4  256           // HW / 4
#define GH   16            // NS*ALPHA
#define EPS  1e-5f

// ---- scratch (tiny, static device globals — no allocation) ----
__device__ float g_theta[NB * C * NS];   // [nb][c][s]
__device__ float g_kcoef[NB * C * KK];   // [nb][c][k]
__device__ float g_u    [NB * CB * NS];  // [nb][cb][s]
__device__ float g_gate [NB * C * NS];   // [nb][c][s]

// ============================================================
// Kernel 1: theta = mean over H*W.  One block per (n, c) plane.
// plane = n*C + c, n = nb*NS + s.  128 threads, 8 floats each.
// ============================================================
__global__ __launch_bounds__(128) void k_theta(const float* __restrict__ x) {
    int plane = blockIdx.x;
    const float4* p = reinterpret_cast<const float4*>(x) + (size_t)plane * HW4;
    int t = threadIdx.x;
    float4 a = p[t];
    float4 b = p[t + 128];
    float s = a.x + a.y + a.z + a.w + b.x + b.y + b.z + b.w;
    #pragma unroll
    for (int o = 16; o > 0; o >>= 1) s += __shfl_down_sync(0xffffffffu, s, o);
    __shared__ float ws[4];
    if ((t & 31) == 0) ws[t >> 5] = s;
    __syncthreads();
    if (t == 0) {
        float tot = ws[0] + ws[1] + ws[2] + ws[3];
        int n  = plane / C, c = plane % C;
        int nb = n / NS,   sg = n % NS;
        g_theta[(nb * C + c) * NS + sg] = tot * (1.0f / HW);
    }
}

// ============================================================
// Kernel 2: G-branch. One thread per (nb,c) row: 8->16 fc, BN,
// relu, 16->3 fc, softmax -> kcoef. Weights broadcast via L2.
// ============================================================
__global__ __launch_bounds__(256) void k_gbranch(
    const float* __restrict__ gw1, const float* __restrict__ gg,
    const float* __restrict__ gb,  const float* __restrict__ gm,
    const float* __restrict__ gv,  const float* __restrict__ gw2) {
    int row = blockIdx.x * 256 + threadIdx.x;     // nb*C + c
    if (row >= NB * C) return;
    float th[NS];
    #pragma unroll
    for (int s = 0; s < NS; s++) th[s] = g_theta[row * NS + s];

    float lg[KK] = {0.f, 0.f, 0.f};
    #pragma unroll
    for (int j = 0; j < GH; j++) {
        float t = 0.f;
        #pragma unroll
        for (int s = 0; s < NS; s++) t += th[s] * __ldg(gw1 + j * NS + s);
        t = (t - __ldg(gm + j)) * rsqrtf(__ldg(gv + j) + EPS) * __ldg(gg + j) + __ldg(gb + j);
        t = fmaxf(t, 0.f);
        #pragma unroll
        for (int k = 0; k < KK; k++) lg[k] += t * __ldg(gw2 + k * GH + j);
    }
    float m = fmaxf(lg[0], fmaxf(lg[1], lg[2]));
    float e0 = __expf(lg[0] - m), e1 = __expf(lg[1] - m), e2 = __expf(lg[2] - m);
    float inv = 1.f / (e0 + e1 + e2);
    g_kcoef[row * KK + 0] = e0 * inv;
    g_kcoef[row * KK + 1] = e1 * inv;
    g_kcoef[row * KK + 2] = e2 * inv;
}

// ============================================================
// Kernel 3: L-branch conv1: u[nb,cb,s] = relu(BN(sum_c sum_dk
// l_w1[cb,c,dk] * theta_pad[nb,c,s+dk-1])).
// Grid: 64 blocks = (nb=8) x (cb-group of 16). 8 warps/block,
// each warp owns 2 cb rows; lanes split c. theta staged in smem
// padded to stride 11 (gcd(11,32)=1 -> conflict-free).
// ============================================================
__global__ __launch_bounds__(256) void k_lconv1(
    const float* __restrict__ lw1, const float* __restrict__ lg,
    const float* __restrict__ lb,  const float* __restrict__ lm,
    const float* __restrict__ lv) {
    __shared__ float thp[C * 11];    // [c][0..9], slot10 pad; col0/col9 are zero-pad
    int nb    = blockIdx.x >> 3;
    int group = blockIdx.x & 7;
    int tid = threadIdx.x;

    for (int idx = tid; idx < C * NS; idx += 256) {
        int c = idx >> 3, s = idx & 7;
        thp[c * 11 + s + 1] = g_theta[(nb * C + c) * NS + s];
    }
    for (int c = tid; c < C; c += 256) {
        thp[c * 11 + 0] = 0.f;
        thp[c * 11 + 9] = 0.f;
    }
    __syncthreads();

    int warp = tid >> 5, lane = tid & 31;
    #pragma unroll
    for (int i = 0; i < 2; i++) {
        int cb = group * 16 + warp * 2 + i;
        const float* wrow = lw1 + (size_t)cb * C * 3;
        float acc[NS] = {0.f,0.f,0.f,0.f,0.f,0.f,0.f,0.f};
        for (int c = lane; c < C; c += 32) {
            float w0 = wrow[c * 3 + 0];
            float w1 = wrow[c * 3 + 1];
            float w2 = wrow[c * 3 + 2];
            const float* tp = &thp[c * 11];
            #pragma unroll
            for (int s = 0; s < NS; s++)
                acc[s] += w0 * tp[s] + w1 * tp[s + 1] + w2 * tp[s + 2];
        }
        #pragma unroll
        for (int s = 0; s < NS; s++)
            #pragma unroll
            for (int o = 16; o > 0; o >>= 1)
                acc[s] += __shfl_down_sync(0xffffffffu, acc[s], o);
        if (lane == 0) {
            float sc = rsqrtf(lv[cb] + EPS) * lg[cb];
            float mu = lm[cb], be = lb[cb];
            #pragma unroll
            for (int s = 0; s < NS; s++) {
                float v = (acc[s] - mu) * sc + be;
                g_u[(nb * CB + cb) * NS + s] = fmaxf(v, 0.f);
            }
        }
    }
}

// ============================================================
// Kernel 4: gate[nb,c,s] = sigmoid(sum_cb l_w2[c,cb] * u[nb,cb,s])
// Warp per (nb,c); lanes split cb (coalesced l_w2 loads).
// ============================================================
__global__ __launch_bounds__(256) void k_lconv2(const float* __restrict__ lw2) {
    int warp = threadIdx.x >> 5, lane = threadIdx.x & 31;
    int row  = blockIdx.x * 8 + warp;       // nb*C + c
    int nb = row >> 9, c = row & (C - 1);
    float acc[NS] = {0.f,0.f,0.f,0.f,0.f,0.f,0.f,0.f};
    for (int cb = lane; cb < CB; cb += 32) {
        float wv = __ldg(lw2 + c * CB + cb);
        const float* up = g_u + (nb * CB + cb) * NS;
        #pragma unroll
        for (int s = 0; s < NS; s++) acc[s] += wv * up[s];
    }
    #pragma unroll
    for (int s = 0; s < NS; s++)
        #pragma unroll
        for (int o = 16; o > 0; o >>= 1)
            acc[s] += __shfl_down_sync(0xffffffffu, acc[s], o);
    if (lane == 0) {
        #pragma unroll
        for (int s = 0; s < NS; s++)
            g_gate[row * NS + s] = 1.f / (1.f + __expf(-acc[s]));
    }
}

// ============================================================
// Kernel 5: y[nb,s,c,hw] = sum_k kcoef[nb,c,k]*gate[nb,c,s+k-1]
//                          * x[nb,s+k-1,c,hw]
// One block per (nb,c); 256 threads x float4 covers HW=1024.
// All 8 segments register-resident -> x read exactly once.
// ============================================================
__global__ __launch_bounds__(256) void k_main(
    const float* __restrict__ x, float* __restrict__ y) {
    __shared__ float w[NS][KK];   // combined weights
    __shared__ float sg[NS + 2];
    __shared__ float sk[KK];
    int nbc = blockIdx.x;         // nb*C + c
    int tid = threadIdx.x;
    if (tid < NS) sg[tid + 1] = g_gate[nbc * NS + tid];
    if (tid == NS) { sg[0] = 0.f; sg[NS + 1] = 0.f; }
    if (tid < KK) sk[tid] = g_kcoef[nbc * KK + tid];
    __syncthreads();
    if (tid < NS * KK) {
        int s = tid / KK, k = tid % KK;
        w[s][k] = sk[k] * sg[s + k];          // gate index s+k-1, +1 pad offset
    }
    __syncthreads();

    int nb = nbc / C, c = nbc % C;
    const float4* xin  = reinterpret_cast<const float4*>(x);
    float4*       yout = reinterpret_cast<float4*>(y);
    int base = ((nb * NS) * C + c) * HW4 + tid;   // float4 index; plane stride C*HW4

    float4 xs[NS];
    #pragma unroll
    for (int s = 0; s < NS; s++) xs[s] = xin[base + s * (C * HW4)];

    #pragma unroll
    for (int s = 0; s < NS; s++) {
        float w0 = w[s][0], w1 = w[s][1], w2 = w[s][2];
        float4 r;
        r.x = w1 * xs[s].x; r.y = w1 * xs[s].y;
        r.z = w1 * xs[s].z; r.w = w1 * xs[s].w;
        if (s > 0) {
            r.x += w0 * xs[s-1].x; r.y += w0 * xs[s-1].y;
            r.z += w0 * xs[s-1].z; r.w += w0 * xs[s-1].w;
        }
        if (s < NS - 1) {
            r.x += w2 * xs[s+1].x; r.y += w2 * xs[s+1].y;
            r.z += w2 * xs[s+1].z; r.w += w2 * xs[s+1].w;
        }
        yout[base + s * (C * HW4)] = r;
    }
}

// ============================================================
extern "C" void kernel_launch(void* const* d_in, const int* in_sizes, int n_in,
                              void* d_out, int out_size) {
    const float* x    = (const float*)d_in[0];
    const float* gw1  = (const float*)d_in[1];
    const float* ggam = (const float*)d_in[2];
    const float* gbet = (const float*)d_in[3];
    const float* gmea = (const float*)d_in[4];
    const float* gvar = (const float*)d_in[5];
    const float* gw2  = (const float*)d_in[6];
    const float* lw1  = (const float*)d_in[7];
    const float* lgam = (const float*)d_in[8];
    const float* lbet = (const float*)d_in[9];
    const float* lmea = (const float*)d_in[10];
    const float* lvar = (const float*)d_in[11];
    const float* lw2  = (const float*)d_in[12];
    float* y = (float*)d_out;

    k_theta  <<<NB * NS * C, 128>>>(x);
    k_gbranch<<<(NB * C + 255) / 256, 256>>>(gw1, ggam, gbet, gmea, gvar, gw2);
    k_lconv1 <<<NB * 8, 256>>>(lw1, lgam, lbet, lmea, lvar);
    k_lconv2 <<<(NB * C) / 8, 256>>>(lw2);
    k_main   <<<NB * C, 256>>>(x, y);
}